// round 1
// baseline (speedup 1.0000x reference)
#include <cuda_runtime.h>

// Problem constants
#define BN   4
#define CN   128
#define HN   128
#define WN   128
#define COUT 128
#define DGN  8
#define CG   16
#define KHN  3
#define KWN  3
#define KK   9
#define HO   128
#define WO   128

// Scratch: x transposed to (B, DG, H, W, Cg) and weight to (DG, K, Cg, Cout)
__device__ __align__(16) float g_xt[BN * DGN * HN * WN * CG];   // 33.5 MB
__device__ __align__(16) float g_wt[DGN * KK * CG * COUT];      // 576 KB

// ---------------------------------------------------------------------------
// Kernel 1: transpose x (B,C,H,W) -> (B, DG, H, W, Cg)
// One block per (b, dg, y); 128 threads over x-coordinate.
// ---------------------------------------------------------------------------
__global__ void transpose_x_kernel(const float* __restrict__ x) {
    int blk = blockIdx.x;          // (b*DGN + dg)*HN + y
    int y   = blk & (HN - 1);
    int bdg = blk >> 7;            // b*DGN + dg
    int b   = bdg >> 3;
    int dg  = bdg & 7;
    int t   = threadIdx.x;         // x coordinate

    __shared__ float sm[CG][WN + 1];
    #pragma unroll
    for (int c = 0; c < CG; c++) {
        sm[c][t] = x[((b * CN + dg * CG + c) * HN + y) * WN + t];
    }
    __syncthreads();

    float* outp = g_xt + ((bdg * HN + y) * WN + t) * CG;
    #pragma unroll
    for (int i = 0; i < 4; i++) {
        float4 v = make_float4(sm[i * 4 + 0][t], sm[i * 4 + 1][t],
                               sm[i * 4 + 2][t], sm[i * 4 + 3][t]);
        *(float4*)(outp + i * 4) = v;
    }
}

// ---------------------------------------------------------------------------
// Kernel 2: transpose weight (Cout, C, K) -> (DG, K, Cg, Cout)
// ---------------------------------------------------------------------------
__global__ void transpose_w_kernel(const float* __restrict__ w) {
    int j = blockIdx.x * 256 + threadIdx.x;
    if (j >= DGN * KK * CG * COUT) return;
    int co = j & (COUT - 1);
    int c  = (j >> 7) & (CG - 1);
    int dk = j >> 11;              // dg*KK + k
    int k  = dk % KK;
    int dg = dk / KK;
    g_wt[j] = w[(co * CN + dg * CG + c) * KK + k];
}

// ---------------------------------------------------------------------------
// Kernel 3: fused deformable sampling + implicit GEMM.
// One block per (b, ho): 128 pixels (full output row) x 128 Cout.
// 256 threads; each owns an 8(co) x 8(px) register tile.
// Per (dg,k) step: threads 0..127 sample 16 channels for their pixel into
// smem; threads 128..255 stage the 16x128 weight slice; then everyone FMAs.
// ---------------------------------------------------------------------------
__global__ __launch_bounds__(256, 2)
void dcn_main_kernel(const float* __restrict__ offset,
                     const float* __restrict__ mask,
                     const float* __restrict__ bias,
                     float*       __restrict__ out) {
    int blk = blockIdx.x;          // b*HO + ho
    int ho  = blk & (HO - 1);
    int b   = blk >> 7;
    int t   = threadIdx.x;

    __shared__ __align__(16) float s_tile[CG][WO];    // sampled values [c][pixel]
    __shared__ __align__(16) float w_tile[CG][COUT];  // weights [c][co]

    int co_base = (t & 15) * 8;
    int p_base  = (t >> 4) * 8;

    float acc[8][8];
    #pragma unroll
    for (int i = 0; i < 8; i++)
        #pragma unroll
        for (int j = 0; j < 8; j++) acc[i][j] = 0.0f;

    for (int dg = 0; dg < DGN; dg++) {
        for (int k = 0; k < KK; k++) {
            __syncthreads();   // previous GEMM phase done reading tiles

            if (t < WO) {
                // ---- sampling for pixel wo = t ----
                int wo = t;
                int ky = k / KWN, kx = k - ky * KWN;
                int och = (dg * KK + k) * 2;
                int oidx = ((b * (2 * DGN * KK) + och) * HO + ho) * WO + wo;
                float dy = offset[oidx];
                float dx = offset[oidx + HO * WO];
                float m  = mask[((b * (DGN * KK) + dg * KK + k) * HO + ho) * WO + wo];

                float sy = dy + (float)(ho - 1 + ky);   // STRIDE=1, PAD=1, DIL=1
                float sx = dx + (float)(wo - 1 + kx);
                float y0f = floorf(sy), x0f = floorf(sx);
                float ly = sy - y0f, lx = sx - x0f;
                int y0 = (int)y0f, x0 = (int)x0f;

                float w00 = (1.0f - ly) * (1.0f - lx) * m;
                float w01 = (1.0f - ly) * lx * m;
                float w10 = ly * (1.0f - lx) * m;
                float w11 = ly * lx * m;

                const float* base = g_xt + (b * DGN + dg) * (HN * WN * CG);

                float val[16];
                #pragma unroll
                for (int c = 0; c < 16; c++) val[c] = 0.0f;

                int ys[4] = {y0, y0, y0 + 1, y0 + 1};
                int xs[4] = {x0, x0 + 1, x0, x0 + 1};
                float ws[4] = {w00, w01, w10, w11};
                #pragma unroll
                for (int cn = 0; cn < 4; cn++) {
                    int yy = ys[cn], xx = xs[cn];
                    if (yy >= 0 && yy < HN && xx >= 0 && xx < WN) {
                        const float4* p = (const float4*)(base + (yy * WN + xx) * CG);
                        float wgt = ws[cn];
                        #pragma unroll
                        for (int i = 0; i < 4; i++) {
                            float4 v = p[i];
                            val[i * 4 + 0] += wgt * v.x;
                            val[i * 4 + 1] += wgt * v.y;
                            val[i * 4 + 2] += wgt * v.z;
                            val[i * 4 + 3] += wgt * v.w;
                        }
                    }
                }
                #pragma unroll
                for (int c = 0; c < 16; c++) s_tile[c][wo] = val[c];
            } else {
                // ---- stage weight slice for this (dg,k): 2048 floats ----
                int tt = t - 128;
                const float4* wsrc = (const float4*)(g_wt + (dg * KK + k) * (CG * COUT));
                float4* wdst = (float4*)&w_tile[0][0];
                #pragma unroll
                for (int i = 0; i < 4; i++) {
                    wdst[tt + i * 128] = wsrc[tt + i * 128];
                }
            }
            __syncthreads();

            // ---- register-blocked GEMM micro-step: 16 channels ----
            #pragma unroll
            for (int c = 0; c < 16; c++) {
                float4 w0 = *(const float4*)&w_tile[c][co_base];
                float4 w1 = *(const float4*)&w_tile[c][co_base + 4];
                float4 s0 = *(const float4*)&s_tile[c][p_base];
                float4 s1 = *(const float4*)&s_tile[c][p_base + 4];
                float wv[8] = {w0.x, w0.y, w0.z, w0.w, w1.x, w1.y, w1.z, w1.w};
                float sv[8] = {s0.x, s0.y, s0.z, s0.w, s1.x, s1.y, s1.z, s1.w};
                #pragma unroll
                for (int i = 0; i < 8; i++)
                    #pragma unroll
                    for (int j = 0; j < 8; j++)
                        acc[i][j] += wv[i] * sv[j];
            }
        }
    }

    // ---- epilogue ----
    #pragma unroll
    for (int i = 0; i < 8; i++) {
        int co = co_base + i;
        float bv = bias[co];
        float* op = out + ((b * COUT + co) * HO + ho) * WO + p_base;
        float4 o0 = make_float4(acc[i][0] + bv, acc[i][1] + bv,
                                acc[i][2] + bv, acc[i][3] + bv);
        float4 o1 = make_float4(acc[i][4] + bv, acc[i][5] + bv,
                                acc[i][6] + bv, acc[i][7] + bv);
        *(float4*)op       = o0;
        *(float4*)(op + 4) = o1;
    }
}

// ---------------------------------------------------------------------------
// Launch
// ---------------------------------------------------------------------------
extern "C" void kernel_launch(void* const* d_in, const int* in_sizes, int n_in,
                              void* d_out, int out_size) {
    const float* x      = (const float*)d_in[0];
    const float* offset = (const float*)d_in[1];
    const float* mask   = (const float*)d_in[2];
    const float* weight = (const float*)d_in[3];
    const float* bias   = (const float*)d_in[4];
    float* out = (float*)d_out;

    transpose_x_kernel<<<BN * DGN * HN, 128>>>(x);
    transpose_w_kernel<<<(DGN * KK * CG * COUT + 255) / 256, 256>>>(weight);
    dcn_main_kernel<<<BN * HO, 256>>>(offset, mask, bias, out);
}

// round 2
// speedup vs baseline: 1.0369x; 1.0369x over previous
#include <cuda_runtime.h>

// Problem constants
#define BN   4
#define CN   128
#define HN   128
#define WN   128
#define COUT 128
#define DGN  8
#define CG   16
#define KHN  3
#define KWN  3
#define KK   9
#define HO   128
#define WO   128

typedef unsigned long long u64;

// Scratch: x transposed to (B, DG, H, W, Cg) and weight to (DG, K, Cg, Cout)
__device__ __align__(16) float g_xt[BN * DGN * HN * WN * CG];   // 33.5 MB
__device__ __align__(16) float g_wt[DGN * KK * CG * COUT];      // 576 KB

__device__ __forceinline__ u64 pack2(float a, float b) {
    u64 r;
    asm("mov.b64 %0, {%1, %2};" : "=l"(r) : "f"(a), "f"(b));
    return r;
}
__device__ __forceinline__ void ffma2(u64& d, u64 a, u64 b) {
    asm("fma.rn.f32x2 %0, %1, %2, %0;" : "+l"(d) : "l"(a), "l"(b));
}

// ---------------------------------------------------------------------------
// Kernel 1: transpose x (B,C,H,W) -> (B, DG, H, W, Cg)
// ---------------------------------------------------------------------------
__global__ void transpose_x_kernel(const float* __restrict__ x) {
    int blk = blockIdx.x;          // (b*DGN + dg)*HN + y
    int y   = blk & (HN - 1);
    int bdg = blk >> 7;            // b*DGN + dg
    int b   = bdg >> 3;
    int dg  = bdg & 7;
    int t   = threadIdx.x;         // x coordinate

    __shared__ float sm[CG][WN + 1];
    #pragma unroll
    for (int c = 0; c < CG; c++) {
        sm[c][t] = x[((b * CN + dg * CG + c) * HN + y) * WN + t];
    }
    __syncthreads();

    float* outp = g_xt + ((bdg * HN + y) * WN + t) * CG;
    #pragma unroll
    for (int i = 0; i < 4; i++) {
        float4 v = make_float4(sm[i * 4 + 0][t], sm[i * 4 + 1][t],
                               sm[i * 4 + 2][t], sm[i * 4 + 3][t]);
        *(float4*)(outp + i * 4) = v;
    }
}

// ---------------------------------------------------------------------------
// Kernel 2: transpose weight (Cout, C, K) -> (DG, K, Cg, Cout)
// ---------------------------------------------------------------------------
__global__ void transpose_w_kernel(const float* __restrict__ w) {
    int j = blockIdx.x * 256 + threadIdx.x;
    if (j >= DGN * KK * CG * COUT) return;
    int co = j & (COUT - 1);
    int c  = (j >> 7) & (CG - 1);
    int dk = j >> 11;              // dg*KK + k
    int k  = dk % KK;
    int dg = dk / KK;
    g_wt[j] = w[(co * CN + dg * CG + c) * KK + k];
}

// ---------------------------------------------------------------------------
// Kernel 3: fused deformable sampling + implicit GEMM with packed f32x2 FMA.
// One block per (b, ho): 128 pixels x 128 Cout, 256 threads.
// Each thread: 8(co) x 8(px) tile held as 8x4 packed f32x2 accumulators.
// Sampling: ALL 256 threads participate — thread t samples pixel (t&127),
// channel-half (t>>7)*8, and stages 8 weight floats.
// ---------------------------------------------------------------------------
__global__ __launch_bounds__(256, 2)
void dcn_main_kernel(const float* __restrict__ offset,
                     const float* __restrict__ mask,
                     const float* __restrict__ bias,
                     float*       __restrict__ out) {
    int blk = blockIdx.x;          // b*HO + ho
    int ho  = blk & (HO - 1);
    int b   = blk >> 7;
    int t   = threadIdx.x;

    __shared__ __align__(16) float s_tile[CG][WO];    // sampled values [c][pixel]
    __shared__ __align__(16) float w_tile[CG][COUT];  // weights [c][co]

    int co_base = (t & 15) * 8;
    int p_base  = (t >> 4) * 8;

    // sampling-role decomposition
    int wo = t & (WO - 1);
    int ch = (t >> 7) * 8;         // 0 or 8: which 8 channels this thread samples

    u64 acc2[8][4];
    #pragma unroll
    for (int i = 0; i < 8; i++)
        #pragma unroll
        for (int j = 0; j < 4; j++) acc2[i][j] = 0ULL;

    for (int dg = 0; dg < DGN; dg++) {
        for (int k = 0; k < KK; k++) {
            __syncthreads();   // previous GEMM phase done reading tiles

            // ---- stage weight slice (2048 floats, 2 float4 per thread) ----
            {
                const float4* wsrc = (const float4*)(g_wt + (dg * KK + k) * (CG * COUT));
                float4* wdst = (float4*)&w_tile[0][0];
                wdst[t]       = wsrc[t];
                wdst[t + 256] = wsrc[t + 256];
            }

            // ---- sampling: 8 channels for pixel wo ----
            {
                int ky = k / KWN, kx = k - ky * KWN;
                int och = (dg * KK + k) * 2;
                int oidx = ((b * (2 * DGN * KK) + och) * HO + ho) * WO + wo;
                float dy = __ldg(offset + oidx);
                float dx = __ldg(offset + oidx + HO * WO);
                float m  = __ldg(mask + ((b * (DGN * KK) + dg * KK + k) * HO + ho) * WO + wo);

                float sy = dy + (float)(ho - 1 + ky);   // STRIDE=1, PAD=1, DIL=1
                float sx = dx + (float)(wo - 1 + kx);
                float y0f = floorf(sy), x0f = floorf(sx);
                float ly = sy - y0f, lx = sx - x0f;
                int y0 = (int)y0f, x0 = (int)x0f;

                float w00 = (1.0f - ly) * (1.0f - lx) * m;
                float w01 = (1.0f - ly) * lx * m;
                float w10 = ly * (1.0f - lx) * m;
                float w11 = ly * lx * m;

                const float* base = g_xt + (b * DGN + dg) * (HN * WN * CG) + ch;

                float val[8];
                #pragma unroll
                for (int c = 0; c < 8; c++) val[c] = 0.0f;

                int   ys[4] = {y0, y0, y0 + 1, y0 + 1};
                int   xs[4] = {x0, x0 + 1, x0, x0 + 1};
                float wb[4] = {w00, w01, w10, w11};
                #pragma unroll
                for (int cn = 0; cn < 4; cn++) {
                    int yy = ys[cn], xx = xs[cn];
                    if (yy >= 0 && yy < HN && xx >= 0 && xx < WN) {
                        const float4* p = (const float4*)(base + (yy * WN + xx) * CG);
                        float wgt = wb[cn];
                        float4 v0 = p[0];
                        float4 v1 = p[1];
                        val[0] += wgt * v0.x;  val[1] += wgt * v0.y;
                        val[2] += wgt * v0.z;  val[3] += wgt * v0.w;
                        val[4] += wgt * v1.x;  val[5] += wgt * v1.y;
                        val[6] += wgt * v1.z;  val[7] += wgt * v1.w;
                    }
                }
                #pragma unroll
                for (int c = 0; c < 8; c++) s_tile[ch + c][wo] = val[c];
            }
            __syncthreads();

            // ---- register-blocked GEMM micro-step: 16 channels, f32x2 ----
            #pragma unroll
            for (int c = 0; c < 16; c++) {
                float4 w0 = *(const float4*)&w_tile[c][co_base];
                float4 w1 = *(const float4*)&w_tile[c][co_base + 4];
                float4 s0 = *(const float4*)&s_tile[c][p_base];
                float4 s1 = *(const float4*)&s_tile[c][p_base + 4];
                u64 sp[4];
                sp[0] = pack2(s0.x, s0.y);
                sp[1] = pack2(s0.z, s0.w);
                sp[2] = pack2(s1.x, s1.y);
                sp[3] = pack2(s1.z, s1.w);
                float wv[8] = {w0.x, w0.y, w0.z, w0.w, w1.x, w1.y, w1.z, w1.w};
                #pragma unroll
                for (int i = 0; i < 8; i++) {
                    u64 wp = pack2(wv[i], wv[i]);
                    ffma2(acc2[i][0], wp, sp[0]);
                    ffma2(acc2[i][1], wp, sp[1]);
                    ffma2(acc2[i][2], wp, sp[2]);
                    ffma2(acc2[i][3], wp, sp[3]);
                }
            }
        }
    }

    // ---- epilogue ----
    union { u64 u; float2 f; } cv;
    #pragma unroll
    for (int i = 0; i < 8; i++) {
        int co = co_base + i;
        float bv = bias[co];
        float r[8];
        #pragma unroll
        for (int j = 0; j < 4; j++) {
            cv.u = acc2[i][j];
            r[2 * j]     = cv.f.x + bv;
            r[2 * j + 1] = cv.f.y + bv;
        }
        float* op = out + ((b * COUT + co) * HO + ho) * WO + p_base;
        *(float4*)op       = make_float4(r[0], r[1], r[2], r[3]);
        *(float4*)(op + 4) = make_float4(r[4], r[5], r[6], r[7]);
    }
}

// ---------------------------------------------------------------------------
// Launch
// ---------------------------------------------------------------------------
extern "C" void kernel_launch(void* const* d_in, const int* in_sizes, int n_in,
                              void* d_out, int out_size) {
    const float* x      = (const float*)d_in[0];
    const float* offset = (const float*)d_in[1];
    const float* mask   = (const float*)d_in[2];
    const float* weight = (const float*)d_in[3];
    const float* bias   = (const float*)d_in[4];
    float* out = (float*)d_out;

    transpose_x_kernel<<<BN * DGN * HN, 128>>>(x);
    transpose_w_kernel<<<(DGN * KK * CG * COUT + 255) / 256, 256>>>(weight);
    dcn_main_kernel<<<BN * HO, 256>>>(offset, mask, bias, out);
}